// round 14
// baseline (speedup 1.0000x reference)
#include <cuda_runtime.h>
#include <cuda_fp16.h>
#include <cuda_bf16.h>
#include <mma.h>
#include <cstddef>

#define NN    100000
#define FIN   128
#define FHID  128
#define FOUT  64
#define EMAX  1600000

using namespace nvcuda;

// ---------------- static scratch ------------------------------------------
__device__ int   g_deg[NN];
__device__ int   g_offs[NN];
__device__ int   g_cursor[NN];
__device__ int   g_csr[EMAX];
__device__ float g_dis[NN];
__device__ __align__(128) __half g_h1s[(size_t)NN * FHID];  // fp16 UNSCALED x@W1
__device__ __align__(128) __half g_h1f[(size_t)NN * FHID];  // fp16 layer-1 output
__device__ __align__(128) __half g_h2s[(size_t)NN * FOUT];  // fp16 dis*(h1f@W2)
__device__ int   g_bsum[1024];
__device__ __align__(128) __nv_bfloat16 g_w1hi[FIN * FHID];
__device__ __align__(128) __nv_bfloat16 g_w1lo[FIN * FHID];
__device__ __align__(128) __nv_bfloat16 g_w2hi[FHID * FOUT];
__device__ __align__(128) __nv_bfloat16 g_w2lo[FHID * FOUT];

// ---------------- helpers ---------------------------------------------------
__device__ __forceinline__ void acc_h4s(float4& s, unsigned lo, unsigned hi, float d) {
    float2 fa = __half22float2(*(__half2*)&lo);
    float2 fb = __half22float2(*(__half2*)&hi);
    s.x = fmaf(d, fa.x, s.x); s.y = fmaf(d, fa.y, s.y);
    s.z = fmaf(d, fb.x, s.z); s.w = fmaf(d, fb.y, s.w);
}
__device__ __forceinline__ void acc_h8s(float4& a, float4& b, uint4 v, float d) {
    acc_h4s(a, v.x, v.y, d);
    acc_h4s(b, v.z, v.w, d);
}
__device__ __forceinline__ void acc_h8(float4& a, float4& b, uint4 v) {
    acc_h4s(a, v.x, v.y, 1.0f);
    acc_h4s(b, v.z, v.w, 1.0f);
}
__device__ __forceinline__ uint2 pack_h4(float a, float b, float c, float d) {
    uint2 r;
    __half2 h0 = __floats2half2_rn(a, b);
    __half2 h1 = __floats2half2_rn(c, d);
    r.x = *(unsigned*)&h0;
    r.y = *(unsigned*)&h1;
    return r;
}
__device__ __forceinline__ void bsplit(float x, __nv_bfloat16& hi, __nv_bfloat16& lo) {
    hi = __float2bfloat16_rn(x);
    lo = __float2bfloat16_rn(x - __bfloat162float(hi));
}
__device__ __forceinline__ void cp_async16(void* dst, const void* src) {
    unsigned d = (unsigned)__cvta_generic_to_shared(dst);
    asm volatile("cp.async.cg.shared.global [%0], [%1], 16;" :: "r"(d), "l"(src));
}
__device__ __forceinline__ void cp_async_commit() {
    asm volatile("cp.async.commit_group;");
}
__device__ __forceinline__ void cp_async_wait0() {
    asm volatile("cp.async.wait_group 0;" ::: "memory");
}

// ---------------- W pre-split ------------------------------------------------
__global__ void wsplit_kernel(const float* __restrict__ W1,
                              const float* __restrict__ W2) {
    int t = blockIdx.x * blockDim.x + threadIdx.x;
    if (t < FIN * FHID) bsplit(W1[t], g_w1hi[t], g_w1lo[t]);
    if (t < FHID * FOUT) bsplit(W2[t], g_w2hi[t], g_w2lo[t]);
}

// ---------------- degree --------------------------------------------------
__global__ void zero_deg_kernel(int M) {
    int t = blockIdx.x * blockDim.x + threadIdx.x;
    if (t < M) g_deg[t] = 0;
}
__global__ void degree_kernel(const int* __restrict__ col, int E) {
    int t = blockIdx.x * blockDim.x + threadIdx.x;
    if (t < E) atomicAdd(&g_deg[col[t]], 1);
}

// ---------------- 2-pass exclusive scan over g_deg --------------------------
__global__ void scan_pass1(int* __restrict__ bsum, int M) {
    __shared__ int sh[8];
    int b = blockIdx.x, t = threadIdx.x;
    int base = b * 1024;
    int v = 0;
#pragma unroll
    for (int k = 0; k < 4; k++) {
        int i = base + t + k * 256;
        if (i < M) v += g_deg[i];
    }
#pragma unroll
    for (int d = 16; d; d >>= 1) v += __shfl_down_sync(0xffffffffu, v, d);
    if ((t & 31) == 0) sh[t >> 5] = v;
    __syncthreads();
    if (t < 8) {
        int x = sh[t];
#pragma unroll
        for (int d = 4; d; d >>= 1) x += __shfl_down_sync(0xffu, x, d);
        if (t == 0) bsum[b] = x;
    }
}
__global__ void scan_pass3(const int* __restrict__ bsum, int M, int nb) {
    __shared__ int wsum[32];
    __shared__ int baseSum;
    int t = threadIdx.x, b = blockIdx.x;
    if (t < 32) {
        int acc = 0;
        for (int i = t; i < b; i += 32) acc += bsum[i];
#pragma unroll
        for (int d = 16; d; d >>= 1) acc += __shfl_down_sync(0xffffffffu, acc, d);
        if (t == 0) baseSum = acc;
    }
    int i = b * 1024 + t;
    int v = (i < M) ? g_deg[i] : 0;
    int lane = t & 31, wid = t >> 5;
    int inc = v;
#pragma unroll
    for (int d = 1; d < 32; d <<= 1) {
        int n = __shfl_up_sync(0xffffffffu, inc, d);
        if (lane >= d) inc += n;
    }
    if (lane == 31) wsum[wid] = inc;
    __syncthreads();
    if (wid == 0) {
        int x = wsum[lane];
        int ix = x;
#pragma unroll
        for (int d = 1; d < 32; d <<= 1) {
            int n = __shfl_up_sync(0xffffffffu, ix, d);
            if (lane >= d) ix += n;
        }
        wsum[lane] = ix - x;
    }
    __syncthreads();
    if (i < M) {
        int excl = inc - v + wsum[wid] + baseSum;
        g_offs[i]   = excl;
        g_cursor[i] = excl;
        g_dis[i]    = rsqrtf((float)(v + 1));
    }
}

// ---------------- CSR placement -------------------------------------------
__global__ void place_kernel(const int* __restrict__ rows,
                             const int* __restrict__ cols, int E) {
    int e = blockIdx.x * blockDim.x + threadIdx.x;
    if (e < E) {
        int c = cols[e];
        int p = atomicAdd(&g_cursor[c], 1);
        g_csr[p] = rows[e];
    }
}

// -------- 3xBF16 tensor GEMM: Ch = half([dis[i] *] (A @ W)) -----------------
template <int BN, bool SCALE, bool HALFA>
__global__ void __launch_bounds__(256, 2)
mma_gemm_kernel(const void* __restrict__ Araw,
                const __nv_bfloat16* __restrict__ Whi,
                const __nv_bfloat16* __restrict__ Wlo,
                __half* __restrict__ Ch, int M)
{
    constexpr int BM  = 64;
    constexpr int K   = 128;
    constexpr int LDA = K + 8;
    constexpr int LDB = BN + 8;
    constexpr int LDC = BN + 4;
    constexpr int FM  = 2, FN = BN / 64;

    extern __shared__ char smem[];
    __nv_bfloat16* Ahi = (__nv_bfloat16*)smem;
    __nv_bfloat16* Alo = Ahi + BM * LDA;
    __nv_bfloat16* Bhi = Alo + BM * LDA;
    __nv_bfloat16* Blo = Bhi + K * LDB;
    float*         Cs  = (float*)smem;

    const int tid = threadIdx.x;
    const int bm0 = blockIdx.x * BM;

    for (int i = tid; i < K * (BN / 8); i += 256) {
        int r  = i / (BN / 8);
        int c8 = (i % (BN / 8)) << 3;
        cp_async16(Bhi + r * LDB + c8, Whi + (size_t)r * BN + c8);
        cp_async16(Blo + r * LDB + c8, Wlo + (size_t)r * BN + c8);
    }
    cp_async_commit();

#pragma unroll
    for (int p = 0; p < 8; p++) {
        int i  = tid + p * 256;
        int r  = i >> 5;
        int c4 = (i & 31) << 2;
        float4 v = make_float4(0.f, 0.f, 0.f, 0.f);
        if (bm0 + r < M) {
            if (HALFA) {
                const __half* Ah = (const __half*)Araw;
                uint2 u = *(const uint2*)(Ah + (size_t)(bm0 + r) * K + c4);
                float2 fa = __half22float2(*(__half2*)&u.x);
                float2 fb = __half22float2(*(__half2*)&u.y);
                v = make_float4(fa.x, fa.y, fb.x, fb.y);
            } else {
                const float* Af = (const float*)Araw;
                v = *(const float4*)(Af + (size_t)(bm0 + r) * K + c4);
            }
        }
        __nv_bfloat16 h0, l0, h1, l1, h2, l2, h3, l3;
        bsplit(v.x, h0, l0); bsplit(v.y, h1, l1);
        bsplit(v.z, h2, l2); bsplit(v.w, h3, l3);
        __nv_bfloat162 hh0 = {h0, h1}, hh1 = {h2, h3};
        __nv_bfloat162 ll0 = {l0, l1}, ll1 = {l2, l3};
        uint2 hp = {*(unsigned*)&hh0, *(unsigned*)&hh1};
        uint2 lp = {*(unsigned*)&ll0, *(unsigned*)&ll1};
        *(uint2*)(Ahi + r * LDA + c4) = hp;
        *(uint2*)(Alo + r * LDA + c4) = lp;
    }
    cp_async_wait0();
    __syncthreads();

    const int warp = tid >> 5;
    const int wm   = warp >> 2;
    const int wn   = warp & 3;
    const int row0 = wm * 32;
    const int col0 = wn * (BN / 4);

    wmma::fragment<wmma::accumulator, 16, 16, 16, float> c[FM][FN];
#pragma unroll
    for (int i = 0; i < FM; i++)
#pragma unroll
        for (int j = 0; j < FN; j++) wmma::fill_fragment(c[i][j], 0.f);

#pragma unroll
    for (int kk = 0; kk < K; kk += 16) {
        wmma::fragment<wmma::matrix_b, 16, 16, 16, __nv_bfloat16, wmma::row_major> bh[FN], bl[FN];
#pragma unroll
        for (int j = 0; j < FN; j++) {
            wmma::load_matrix_sync(bh[j], Bhi + kk * LDB + col0 + j * 16, LDB);
            wmma::load_matrix_sync(bl[j], Blo + kk * LDB + col0 + j * 16, LDB);
        }
#pragma unroll
        for (int i = 0; i < FM; i++) {
            wmma::fragment<wmma::matrix_a, 16, 16, 16, __nv_bfloat16, wmma::row_major> ah, al;
            wmma::load_matrix_sync(ah, Ahi + (row0 + i * 16) * LDA + kk, LDA);
            wmma::load_matrix_sync(al, Alo + (row0 + i * 16) * LDA + kk, LDA);
#pragma unroll
            for (int j = 0; j < FN; j++) {
                wmma::mma_sync(c[i][j], ah, bh[j], c[i][j]);
                wmma::mma_sync(c[i][j], ah, bl[j], c[i][j]);
                wmma::mma_sync(c[i][j], al, bh[j], c[i][j]);
            }
        }
    }

    __syncthreads();
#pragma unroll
    for (int i = 0; i < FM; i++)
#pragma unroll
        for (int j = 0; j < FN; j++)
            wmma::store_matrix_sync(Cs + (row0 + i * 16) * LDC + col0 + j * 16,
                                    c[i][j], LDC, wmma::mem_row_major);
    __syncthreads();

    for (int i = tid; i < BM * (BN / 4); i += 256) {
        int r  = i / (BN / 4);
        int c4 = (i % (BN / 4)) << 2;
        int gr = bm0 + r;
        if (gr < M) {
            float d = SCALE ? g_dis[gr] : 1.0f;
            const float* cp = Cs + r * LDC + c4;
            uint2 p = pack_h4(cp[0] * d, cp[1] * d, cp[2] * d, cp[3] * d);
            *(uint2*)(Ch + (size_t)gr * BN + c4) = p;
        }
    }
}

// ------- agg1: HALF-warp/node, uint4 (16B) gathers; dis[src] at gather ------
// h1f = half(relu(dis[w]*(sum_src dis[src]*h1s[src] + dis[w]*h1s[w]) + b1))
__global__ void __launch_bounds__(256)
agg1_kernel(const float* __restrict__ b1, int M) {
    int tid  = blockIdx.x * 256 + threadIdx.x;
    int node = tid >> 4;                    // half-warp per node
    int lane = threadIdx.x & 31;
    int l16  = lane & 15;
    unsigned mask = 0xFFFFu << (lane & 16);
    bool valid = node < M;
    int beg = 0, end = 0;
    float dw = 0.f;
    if (valid) {
        beg = g_offs[node];
        end = beg + g_deg[node];
        dw  = g_dis[node];
    }
    const uint4* h = (const uint4*)g_h1s;   // 16 x uint4 per row (256 B)
    float4 sa = make_float4(0.f, 0.f, 0.f, 0.f);
    float4 sb = make_float4(0.f, 0.f, 0.f, 0.f);
    if (valid) acc_h8s(sa, sb, __ldg(h + (size_t)node * 16 + l16), dw);
    for (int j0 = beg; j0 < end; j0 += 16) {
        int rem = end - j0;
        int cnt = rem < 16 ? rem : 16;
        int   myi = 0;
        float myd = 0.f;
        if (l16 < rem) {
            myi = __ldg(g_csr + j0 + l16);
            myd = __ldg(g_dis + myi);
        }
        int j = 0;
        for (; j + 4 <= cnt; j += 4) {
            int   s0 = __shfl_sync(mask, myi, j,     16);
            int   s1 = __shfl_sync(mask, myi, j + 1, 16);
            int   s2 = __shfl_sync(mask, myi, j + 2, 16);
            int   s3 = __shfl_sync(mask, myi, j + 3, 16);
            float d0 = __shfl_sync(mask, myd, j,     16);
            float d1 = __shfl_sync(mask, myd, j + 1, 16);
            float d2 = __shfl_sync(mask, myd, j + 2, 16);
            float d3 = __shfl_sync(mask, myd, j + 3, 16);
            uint4 v0 = __ldg(h + (size_t)s0 * 16 + l16);
            uint4 v1 = __ldg(h + (size_t)s1 * 16 + l16);
            uint4 v2 = __ldg(h + (size_t)s2 * 16 + l16);
            uint4 v3 = __ldg(h + (size_t)s3 * 16 + l16);
            acc_h8s(sa, sb, v0, d0); acc_h8s(sa, sb, v1, d1);
            acc_h8s(sa, sb, v2, d2); acc_h8s(sa, sb, v3, d3);
        }
        for (; j < cnt; j++) {
            int   si = __shfl_sync(mask, myi, j, 16);
            float di = __shfl_sync(mask, myd, j, 16);
            acc_h8s(sa, sb, __ldg(h + (size_t)si * 16 + l16), di);
        }
    }
    if (valid) {
        float4 ba = __ldg((const float4*)b1 + l16 * 2);
        float4 bb = __ldg((const float4*)b1 + l16 * 2 + 1);
        float o0 = fmaxf(fmaf(dw, sa.x, ba.x), 0.f);
        float o1 = fmaxf(fmaf(dw, sa.y, ba.y), 0.f);
        float o2 = fmaxf(fmaf(dw, sa.z, ba.z), 0.f);
        float o3 = fmaxf(fmaf(dw, sa.w, ba.w), 0.f);
        float o4 = fmaxf(fmaf(dw, sb.x, bb.x), 0.f);
        float o5 = fmaxf(fmaf(dw, sb.y, bb.y), 0.f);
        float o6 = fmaxf(fmaf(dw, sb.z, bb.z), 0.f);
        float o7 = fmaxf(fmaf(dw, sb.w, bb.w), 0.f);
        uint2 p0 = pack_h4(o0, o1, o2, o3);
        uint2 p1 = pack_h4(o4, o5, o6, o7);
        uint4 p = make_uint4(p0.x, p0.y, p1.x, p1.y);
        ((uint4*)g_h1f)[(size_t)node * 16 + l16] = p;
    }
}

// ------- agg2: QUARTER-warp/node, uint4 gathers ------------------------------
// out = dis*(sum_nbr h2s + h2s[self]) + b2
__global__ void __launch_bounds__(256)
agg2_kernel(float* __restrict__ out, const float* __restrict__ b2, int M) {
    int tid  = blockIdx.x * 256 + threadIdx.x;
    int node = tid >> 3;                    // quarter-warp per node
    int lane = threadIdx.x & 31;
    int l8   = lane & 7;
    unsigned mask = 0xFFu << (lane & 24);
    bool valid = node < M;
    int beg = 0, end = 0;
    if (valid) { beg = g_offs[node]; end = beg + g_deg[node]; }
    const uint4* h = (const uint4*)g_h2s;   // 8 x uint4 per row (128 B)
    float4 sa = make_float4(0.f, 0.f, 0.f, 0.f);
    float4 sb = make_float4(0.f, 0.f, 0.f, 0.f);
    if (valid) acc_h8(sa, sb, __ldg(h + (size_t)node * 8 + l8));
    for (int j0 = beg; j0 < end; j0 += 8) {
        int rem = end - j0;
        int cnt = rem < 8 ? rem : 8;
        int myi = (l8 < rem) ? __ldg(g_csr + j0 + l8) : 0;
        int j = 0;
        for (; j + 4 <= cnt; j += 4) {
            int s0 = __shfl_sync(mask, myi, j,     8);
            int s1 = __shfl_sync(mask, myi, j + 1, 8);
            int s2 = __shfl_sync(mask, myi, j + 2, 8);
            int s3 = __shfl_sync(mask, myi, j + 3, 8);
            uint4 v0 = __ldg(h + (size_t)s0 * 8 + l8);
            uint4 v1 = __ldg(h + (size_t)s1 * 8 + l8);
            uint4 v2 = __ldg(h + (size_t)s2 * 8 + l8);
            uint4 v3 = __ldg(h + (size_t)s3 * 8 + l8);
            acc_h8(sa, sb, v0); acc_h8(sa, sb, v1);
            acc_h8(sa, sb, v2); acc_h8(sa, sb, v3);
        }
        for (; j < cnt; j++) {
            int si = __shfl_sync(mask, myi, j, 8);
            acc_h8(sa, sb, __ldg(h + (size_t)si * 8 + l8));
        }
    }
    if (valid) {
        float  d = g_dis[node];
        float4 ba = __ldg((const float4*)b2 + l8 * 2);
        float4 bb = __ldg((const float4*)b2 + l8 * 2 + 1);
        float4 oa, ob;
        oa.x = fmaf(d, sa.x, ba.x); oa.y = fmaf(d, sa.y, ba.y);
        oa.z = fmaf(d, sa.z, ba.z); oa.w = fmaf(d, sa.w, ba.w);
        ob.x = fmaf(d, sb.x, bb.x); ob.y = fmaf(d, sb.y, bb.y);
        ob.z = fmaf(d, sb.z, bb.z); ob.w = fmaf(d, sb.w, bb.w);
        float4* op = (float4*)(out + (size_t)node * 64 + l8 * 8);
        op[0] = oa;
        op[1] = ob;
    }
}

// ---------------- launch ----------------------------------------------------
extern "C" void kernel_launch(void* const* d_in, const int* in_sizes, int n_in,
                              void* d_out, int out_size) {
    const float* x  = (const float*)d_in[0];
    const int*   ei = (const int*)  d_in[1];
    const float* W1 = (const float*)d_in[2];
    const float* b1 = (const float*)d_in[3];
    const float* W2 = (const float*)d_in[4];
    const float* b2 = (const float*)d_in[5];
    float* out = (float*)d_out;

    const int M = in_sizes[0] / FIN;
    const int E = in_sizes[1] / 2;
    const int* rows = ei;
    const int* cols = ei + E;

    __half *h1s, *h1f, *h2s;
    int* bsum;
    __nv_bfloat16 *w1hi, *w1lo, *w2hi, *w2lo;
    cudaGetSymbolAddress((void**)&h1s,  g_h1s);
    cudaGetSymbolAddress((void**)&h1f,  g_h1f);
    cudaGetSymbolAddress((void**)&h2s,  g_h2s);
    cudaGetSymbolAddress((void**)&bsum, g_bsum);
    cudaGetSymbolAddress((void**)&w1hi, g_w1hi);
    cudaGetSymbolAddress((void**)&w1lo, g_w1lo);
    cudaGetSymbolAddress((void**)&w2hi, g_w2hi);
    cudaGetSymbolAddress((void**)&w2lo, g_w2lo);

    const int nb = (M + 1023) / 1024;

    const int smem1 = (2 * 64 * 136 + 2 * 128 * 136) * 2;   // 104448
    const int smem2 = (2 * 64 * 136 + 2 * 128 *  72) * 2;   //  71680
    cudaFuncSetAttribute((const void*)mma_gemm_kernel<128, false, false>,
                         cudaFuncAttributeMaxDynamicSharedMemorySize, smem1);
    cudaFuncSetAttribute((const void*)mma_gemm_kernel<64, true, true>,
                         cudaFuncAttributeMaxDynamicSharedMemorySize, smem2);

    static cudaStream_t s2 = nullptr;
    static cudaEvent_t  evFork = nullptr, evG1 = nullptr;
    if (!s2) {
        cudaStreamCreateWithFlags(&s2, cudaStreamNonBlocking);
        cudaEventCreateWithFlags(&evFork, cudaEventDisableTiming);
        cudaEventCreateWithFlags(&evG1,  cudaEventDisableTiming);
    }

    // fork: side stream computes wsplit -> gemm1 while main builds the CSR
    cudaEventRecord(evFork, 0);
    cudaStreamWaitEvent(s2, evFork, 0);

    wsplit_kernel<<<(FIN * FHID + 255) / 256, 256, 0, s2>>>(W1, W2);
    mma_gemm_kernel<128, false, false><<<(M + 63) / 64, 256, smem1, s2>>>(x, w1hi, w1lo, h1s, M);
    cudaEventRecord(evG1, s2);

    zero_deg_kernel<<<(M + 255) / 256, 256>>>(M);
    degree_kernel<<<(E + 255) / 256, 256>>>(cols, E);
    scan_pass1<<<nb, 256>>>(bsum, M);
    scan_pass3<<<nb, 1024>>>(bsum, M, nb);
    place_kernel<<<(E + 255) / 256, 256>>>(rows, cols, E);

    // join: agg1 needs CSR + dis (main) and h1s (side)
    cudaStreamWaitEvent(0, evG1, 0);

    agg1_kernel<<<(M * 16 + 255) / 256, 256>>>(b1, M);
    mma_gemm_kernel<64, true, true><<<(M + 63) / 64, 256, smem2>>>(h1f, w2hi, w2lo, h2s, M);
    agg2_kernel<<<(M * 8 + 255) / 256, 256>>>(out, b2, M);
}

// round 15
// speedup vs baseline: 1.0816x; 1.0816x over previous
#include <cuda_runtime.h>
#include <cuda_fp16.h>
#include <cuda_bf16.h>
#include <mma.h>
#include <cstddef>

#define NN    100000
#define FIN   128
#define FHID  128
#define FOUT  64
#define EMAX  1600000

using namespace nvcuda;

// ---------------- static scratch ------------------------------------------
__device__ int   g_deg[NN];
__device__ int   g_offs[NN];
__device__ int   g_cursor[NN];
__device__ int   g_csr[EMAX];
__device__ float g_dis[NN];
__device__ __align__(128) __half g_h1s[(size_t)NN * FHID];  // fp16 UNSCALED x@W1
__device__ __align__(128) __half g_h1f[(size_t)NN * FHID];  // fp16 layer-1 output
__device__ __align__(128) __half g_h2s[(size_t)NN * FOUT];  // fp16 dis*(h1f@W2)
__device__ int   g_bsum[1024];
__device__ __align__(128) __nv_bfloat16 g_w1hi[FIN * FHID];
__device__ __align__(128) __nv_bfloat16 g_w1lo[FIN * FHID];
__device__ __align__(128) __nv_bfloat16 g_w2hi[FHID * FOUT];
__device__ __align__(128) __nv_bfloat16 g_w2lo[FHID * FOUT];

// ---------------- helpers ---------------------------------------------------
__device__ __forceinline__ void acc_h4(float4& s, uint2 v) {
    float2 fa = __half22float2(*(__half2*)&v.x);
    float2 fb = __half22float2(*(__half2*)&v.y);
    s.x += fa.x; s.y += fa.y; s.z += fb.x; s.w += fb.y;
}
__device__ __forceinline__ void acc_h4s(float4& s, uint2 v, float d) {
    float2 fa = __half22float2(*(__half2*)&v.x);
    float2 fb = __half22float2(*(__half2*)&v.y);
    s.x = fmaf(d, fa.x, s.x); s.y = fmaf(d, fa.y, s.y);
    s.z = fmaf(d, fb.x, s.z); s.w = fmaf(d, fb.y, s.w);
}
__device__ __forceinline__ uint2 pack_h4(float a, float b, float c, float d) {
    uint2 r;
    __half2 h0 = __floats2half2_rn(a, b);
    __half2 h1 = __floats2half2_rn(c, d);
    r.x = *(unsigned*)&h0;
    r.y = *(unsigned*)&h1;
    return r;
}
__device__ __forceinline__ void bsplit(float x, __nv_bfloat16& hi, __nv_bfloat16& lo) {
    hi = __float2bfloat16_rn(x);
    lo = __float2bfloat16_rn(x - __bfloat162float(hi));
}
__device__ __forceinline__ void cp_async16(void* dst, const void* src) {
    unsigned d = (unsigned)__cvta_generic_to_shared(dst);
    asm volatile("cp.async.cg.shared.global [%0], [%1], 16;" :: "r"(d), "l"(src));
}
__device__ __forceinline__ void cp_async_commit() {
    asm volatile("cp.async.commit_group;");
}
__device__ __forceinline__ void cp_async_wait0() {
    asm volatile("cp.async.wait_group 0;" ::: "memory");
}

// ---------------- pre-fork: W pre-split + deg zero ---------------------------
__global__ void wsplit_zero_kernel(const float* __restrict__ W1,
                                   const float* __restrict__ W2, int M) {
    int t = blockIdx.x * blockDim.x + threadIdx.x;
    if (t < FIN * FHID) bsplit(W1[t], g_w1hi[t], g_w1lo[t]);
    if (t < FHID * FOUT) bsplit(W2[t], g_w2hi[t], g_w2lo[t]);
    // zero g_deg (M <= 131072 = 512 blocks x 256)
    if (t < M) g_deg[t] = 0;
}

// ---------------- degree --------------------------------------------------
__global__ void degree_kernel(const int* __restrict__ col, int E) {
    int t = blockIdx.x * blockDim.x + threadIdx.x;
    if (t < E) atomicAdd(&g_deg[col[t]], 1);
}

// ---------------- 2-pass exclusive scan over g_deg --------------------------
__global__ void scan_pass1(int* __restrict__ bsum, int M) {
    __shared__ int sh[8];
    int b = blockIdx.x, t = threadIdx.x;
    int base = b * 1024;
    int v = 0;
#pragma unroll
    for (int k = 0; k < 4; k++) {
        int i = base + t + k * 256;
        if (i < M) v += g_deg[i];
    }
#pragma unroll
    for (int d = 16; d; d >>= 1) v += __shfl_down_sync(0xffffffffu, v, d);
    if ((t & 31) == 0) sh[t >> 5] = v;
    __syncthreads();
    if (t < 8) {
        int x = sh[t];
#pragma unroll
        for (int d = 4; d; d >>= 1) x += __shfl_down_sync(0xffu, x, d);
        if (t == 0) bsum[b] = x;
    }
}
__global__ void scan_pass3(const int* __restrict__ bsum, int M, int nb) {
    __shared__ int wsum[32];
    __shared__ int baseSum;
    int t = threadIdx.x, b = blockIdx.x;
    if (t < 32) {
        int acc = 0;
        for (int i = t; i < b; i += 32) acc += bsum[i];
#pragma unroll
        for (int d = 16; d; d >>= 1) acc += __shfl_down_sync(0xffffffffu, acc, d);
        if (t == 0) baseSum = acc;
    }
    int i = b * 1024 + t;
    int v = (i < M) ? g_deg[i] : 0;
    int lane = t & 31, wid = t >> 5;
    int inc = v;
#pragma unroll
    for (int d = 1; d < 32; d <<= 1) {
        int n = __shfl_up_sync(0xffffffffu, inc, d);
        if (lane >= d) inc += n;
    }
    if (lane == 31) wsum[wid] = inc;
    __syncthreads();
    if (wid == 0) {
        int x = wsum[lane];
        int ix = x;
#pragma unroll
        for (int d = 1; d < 32; d <<= 1) {
            int n = __shfl_up_sync(0xffffffffu, ix, d);
            if (lane >= d) ix += n;
        }
        wsum[lane] = ix - x;
    }
    __syncthreads();
    if (i < M) {
        int excl = inc - v + wsum[wid] + baseSum;
        g_offs[i]   = excl;
        g_cursor[i] = excl;
        g_dis[i]    = rsqrtf((float)(v + 1));
    }
}

// ---------------- CSR placement -------------------------------------------
__global__ void place_kernel(const int* __restrict__ rows,
                             const int* __restrict__ cols, int E) {
    int e = blockIdx.x * blockDim.x + threadIdx.x;
    if (e < E) {
        int c = cols[e];
        int p = atomicAdd(&g_cursor[c], 1);
        g_csr[p] = rows[e];
    }
}

// -------- 3xBF16 tensor GEMM: Ch = half([dis[i] *] (A @ W)) -----------------
// HALFA: A is fp16 (h1f); else fp32. W staged via cp.async.
template <int BN, bool SCALE, bool HALFA, int MINB>
__global__ void __launch_bounds__(256, MINB)
mma_gemm_kernel(const void* __restrict__ Araw,
                const __nv_bfloat16* __restrict__ Whi,
                const __nv_bfloat16* __restrict__ Wlo,
                __half* __restrict__ Ch, int M)
{
    constexpr int BM  = 64;
    constexpr int K   = 128;
    constexpr int LDA = K + 8;
    constexpr int LDB = BN + 8;
    constexpr int LDC = BN + 4;
    constexpr int FM  = 2, FN = BN / 64;

    extern __shared__ char smem[];
    __nv_bfloat16* Ahi = (__nv_bfloat16*)smem;
    __nv_bfloat16* Alo = Ahi + BM * LDA;
    __nv_bfloat16* Bhi = Alo + BM * LDA;
    __nv_bfloat16* Blo = Bhi + K * LDB;
    float*         Cs  = (float*)smem;

    const int tid = threadIdx.x;
    const int bm0 = blockIdx.x * BM;

    // ---- W staging via cp.async (DMA overlaps the A split below) ----
    for (int i = tid; i < K * (BN / 8); i += 256) {
        int r  = i / (BN / 8);
        int c8 = (i % (BN / 8)) << 3;
        cp_async16(Bhi + r * LDB + c8, Whi + (size_t)r * BN + c8);
        cp_async16(Blo + r * LDB + c8, Wlo + (size_t)r * BN + c8);
    }
    cp_async_commit();

    // ---- load + split A tile (64 x 128) ----
#pragma unroll
    for (int p = 0; p < 8; p++) {
        int i  = tid + p * 256;
        int r  = i >> 5;
        int c4 = (i & 31) << 2;
        float4 v = make_float4(0.f, 0.f, 0.f, 0.f);
        if (bm0 + r < M) {
            if (HALFA) {
                const __half* Ah = (const __half*)Araw;
                uint2 u = *(const uint2*)(Ah + (size_t)(bm0 + r) * K + c4);
                float2 fa = __half22float2(*(__half2*)&u.x);
                float2 fb = __half22float2(*(__half2*)&u.y);
                v = make_float4(fa.x, fa.y, fb.x, fb.y);
            } else {
                const float* Af = (const float*)Araw;
                v = *(const float4*)(Af + (size_t)(bm0 + r) * K + c4);
            }
        }
        __nv_bfloat16 h0, l0, h1, l1, h2, l2, h3, l3;
        bsplit(v.x, h0, l0); bsplit(v.y, h1, l1);
        bsplit(v.z, h2, l2); bsplit(v.w, h3, l3);
        __nv_bfloat162 hh0 = {h0, h1}, hh1 = {h2, h3};
        __nv_bfloat162 ll0 = {l0, l1}, ll1 = {l2, l3};
        uint2 hp = {*(unsigned*)&hh0, *(unsigned*)&hh1};
        uint2 lp = {*(unsigned*)&ll0, *(unsigned*)&ll1};
        *(uint2*)(Ahi + r * LDA + c4) = hp;
        *(uint2*)(Alo + r * LDA + c4) = lp;
    }
    cp_async_wait0();
    __syncthreads();

    const int warp = tid >> 5;
    const int wm   = warp >> 2;
    const int wn   = warp & 3;
    const int row0 = wm * 32;
    const int col0 = wn * (BN / 4);

    wmma::fragment<wmma::accumulator, 16, 16, 16, float> c[FM][FN];
#pragma unroll
    for (int i = 0; i < FM; i++)
#pragma unroll
        for (int j = 0; j < FN; j++) wmma::fill_fragment(c[i][j], 0.f);

#pragma unroll
    for (int kk = 0; kk < K; kk += 16) {
        wmma::fragment<wmma::matrix_b, 16, 16, 16, __nv_bfloat16, wmma::row_major> bh[FN], bl[FN];
#pragma unroll
        for (int j = 0; j < FN; j++) {
            wmma::load_matrix_sync(bh[j], Bhi + kk * LDB + col0 + j * 16, LDB);
            wmma::load_matrix_sync(bl[j], Blo + kk * LDB + col0 + j * 16, LDB);
        }
#pragma unroll
        for (int i = 0; i < FM; i++) {
            wmma::fragment<wmma::matrix_a, 16, 16, 16, __nv_bfloat16, wmma::row_major> ah, al;
            wmma::load_matrix_sync(ah, Ahi + (row0 + i * 16) * LDA + kk, LDA);
            wmma::load_matrix_sync(al, Alo + (row0 + i * 16) * LDA + kk, LDA);
#pragma unroll
            for (int j = 0; j < FN; j++) {
                wmma::mma_sync(c[i][j], ah, bh[j], c[i][j]);
                wmma::mma_sync(c[i][j], ah, bl[j], c[i][j]);
                wmma::mma_sync(c[i][j], al, bh[j], c[i][j]);
            }
        }
    }

    __syncthreads();
#pragma unroll
    for (int i = 0; i < FM; i++)
#pragma unroll
        for (int j = 0; j < FN; j++)
            wmma::store_matrix_sync(Cs + (row0 + i * 16) * LDC + col0 + j * 16,
                                    c[i][j], LDC, wmma::mem_row_major);
    __syncthreads();

    for (int i = tid; i < BM * (BN / 4); i += 256) {
        int r  = i / (BN / 4);
        int c4 = (i % (BN / 4)) << 2;
        int gr = bm0 + r;
        if (gr < M) {
            float d = SCALE ? g_dis[gr] : 1.0f;
            const float* cp = Cs + r * LDC + c4;
            uint2 p = pack_h4(cp[0] * d, cp[1] * d, cp[2] * d, cp[3] * d);
            *(uint2*)(Ch + (size_t)gr * BN + c4) = p;
        }
    }
}

// ------- agg1: warp/node; h1s UNSCALED; dis[src] applied at gather ----------
__global__ void __launch_bounds__(256)
agg1_kernel(const float* __restrict__ b1, int M) {
    int w    = (blockIdx.x * 256 + threadIdx.x) >> 5;
    int lane = threadIdx.x & 31;
    if (w >= M) return;
    int beg = g_offs[w];
    int end = beg + g_deg[w];
    float dw = g_dis[w];
    const uint2* h = (const uint2*)g_h1s;
    float4 s = make_float4(0.f, 0.f, 0.f, 0.f);
    acc_h4s(s, __ldg(h + (size_t)w * 32 + lane), dw);   // self * dis[w]
    for (int j0 = beg; j0 < end; j0 += 32) {
        int rem = end - j0;
        int cnt = rem < 32 ? rem : 32;
        int   myi = 0;
        float myd = 0.f;
        if (lane < rem) {
            myi = __ldg(g_csr + j0 + lane);
            myd = __ldg(g_dis + myi);
        }
        int j = 0;
        for (; j + 4 <= cnt; j += 4) {
            int   s0 = __shfl_sync(0xffffffffu, myi, j);
            int   s1 = __shfl_sync(0xffffffffu, myi, j + 1);
            int   s2 = __shfl_sync(0xffffffffu, myi, j + 2);
            int   s3 = __shfl_sync(0xffffffffu, myi, j + 3);
            float d0 = __shfl_sync(0xffffffffu, myd, j);
            float d1 = __shfl_sync(0xffffffffu, myd, j + 1);
            float d2 = __shfl_sync(0xffffffffu, myd, j + 2);
            float d3 = __shfl_sync(0xffffffffu, myd, j + 3);
            uint2 v0 = __ldg(h + (size_t)s0 * 32 + lane);
            uint2 v1 = __ldg(h + (size_t)s1 * 32 + lane);
            uint2 v2 = __ldg(h + (size_t)s2 * 32 + lane);
            uint2 v3 = __ldg(h + (size_t)s3 * 32 + lane);
            acc_h4s(s, v0, d0); acc_h4s(s, v1, d1);
            acc_h4s(s, v2, d2); acc_h4s(s, v3, d3);
        }
        for (; j < cnt; j++) {
            int   si = __shfl_sync(0xffffffffu, myi, j);
            float di = __shfl_sync(0xffffffffu, myd, j);
            acc_h4s(s, __ldg(h + (size_t)si * 32 + lane), di);
        }
    }
    float4 b = __ldg((const float4*)b1 + lane);
    float ox = fmaxf(fmaf(dw, s.x, b.x), 0.f);
    float oy = fmaxf(fmaf(dw, s.y, b.y), 0.f);
    float oz = fmaxf(fmaf(dw, s.z, b.z), 0.f);
    float ow = fmaxf(fmaf(dw, s.w, b.w), 0.f);
    ((uint2*)g_h1f)[(size_t)w * 32 + lane] = pack_h4(ox, oy, oz, ow);
}

// ------- agg2: half-warp/node, out = dis*(sum_nbr h2s + h2s[self]) + b2 ----
__global__ void __launch_bounds__(256)
agg2_kernel(float* __restrict__ out, const float* __restrict__ b2, int M) {
    int tid  = blockIdx.x * 256 + threadIdx.x;
    int node = tid >> 4;
    int lane = threadIdx.x & 31;
    int l16  = lane & 15;
    unsigned mask = 0xFFFFu << (lane & 16);
    bool valid = node < M;
    int beg = 0, end = 0;
    if (valid) { beg = g_offs[node]; end = beg + g_deg[node]; }
    const uint2* h = (const uint2*)g_h2s;
    float4 s = make_float4(0.f, 0.f, 0.f, 0.f);
    if (valid) acc_h4(s, __ldg(h + (size_t)node * 16 + l16));
    for (int j0 = beg; j0 < end; j0 += 16) {
        int rem = end - j0;
        int cnt = rem < 16 ? rem : 16;
        int myi = (l16 < rem) ? __ldg(g_csr + j0 + l16) : 0;
        int j = 0;
        for (; j + 4 <= cnt; j += 4) {
            int s0 = __shfl_sync(mask, myi, j,     16);
            int s1 = __shfl_sync(mask, myi, j + 1, 16);
            int s2 = __shfl_sync(mask, myi, j + 2, 16);
            int s3 = __shfl_sync(mask, myi, j + 3, 16);
            uint2 v0 = __ldg(h + (size_t)s0 * 16 + l16);
            uint2 v1 = __ldg(h + (size_t)s1 * 16 + l16);
            uint2 v2 = __ldg(h + (size_t)s2 * 16 + l16);
            uint2 v3 = __ldg(h + (size_t)s3 * 16 + l16);
            acc_h4(s, v0); acc_h4(s, v1); acc_h4(s, v2); acc_h4(s, v3);
        }
        for (; j < cnt; j++) {
            int si = __shfl_sync(mask, myi, j, 16);
            acc_h4(s, __ldg(h + (size_t)si * 16 + l16));
        }
    }
    if (valid) {
        float  d = g_dis[node];
        float4 b = __ldg((const float4*)b2 + l16);
        float4 o;
        o.x = fmaf(d, s.x, b.x);
        o.y = fmaf(d, s.y, b.y);
        o.z = fmaf(d, s.z, b.z);
        o.w = fmaf(d, s.w, b.w);
        ((float4*)out)[(size_t)node * 16 + l16] = o;
    }
}

// ---------------- launch ----------------------------------------------------
extern "C" void kernel_launch(void* const* d_in, const int* in_sizes, int n_in,
                              void* d_out, int out_size) {
    const float* x  = (const float*)d_in[0];
    const int*   ei = (const int*)  d_in[1];
    const float* W1 = (const float*)d_in[2];
    const float* b1 = (const float*)d_in[3];
    const float* W2 = (const float*)d_in[4];
    const float* b2 = (const float*)d_in[5];
    float* out = (float*)d_out;

    const int M = in_sizes[0] / FIN;
    const int E = in_sizes[1] / 2;
    const int* rows = ei;
    const int* cols = ei + E;

    __half *h1s, *h1f, *h2s;
    int* bsum;
    __nv_bfloat16 *w1hi, *w1lo, *w2hi, *w2lo;
    cudaGetSymbolAddress((void**)&h1s,  g_h1s);
    cudaGetSymbolAddress((void**)&h1f,  g_h1f);
    cudaGetSymbolAddress((void**)&h2s,  g_h2s);
    cudaGetSymbolAddress((void**)&bsum, g_bsum);
    cudaGetSymbolAddress((void**)&w1hi, g_w1hi);
    cudaGetSymbolAddress((void**)&w1lo, g_w1lo);
    cudaGetSymbolAddress((void**)&w2hi, g_w2hi);
    cudaGetSymbolAddress((void**)&w2lo, g_w2lo);

    const int nb = (M + 1023) / 1024;

    const int smem1 = (2 * 64 * 136 + 2 * 128 * 136) * 2;   // 104448
    const int smem2 = (2 * 64 * 136 + 2 * 128 *  72) * 2;   //  71680
    cudaFuncSetAttribute((const void*)mma_gemm_kernel<128, false, false, 2>,
                         cudaFuncAttributeMaxDynamicSharedMemorySize, smem1);
    cudaFuncSetAttribute((const void*)mma_gemm_kernel<64, true, true, 3>,
                         cudaFuncAttributeMaxDynamicSharedMemorySize, smem2);

    static cudaStream_t s2 = nullptr;
    static cudaEvent_t  evFork = nullptr, evG1 = nullptr;
    if (!s2) {
        cudaStreamCreateWithFlags(&s2, cudaStreamNonBlocking);
        cudaEventCreateWithFlags(&evFork, cudaEventDisableTiming);
        cudaEventCreateWithFlags(&evG1,  cudaEventDisableTiming);
    }

    // pre-fork: one kernel does W split + deg zero (both branches need it)
    int preN = (M > FIN * FHID) ? M : FIN * FHID;
    wsplit_zero_kernel<<<(preN + 255) / 256, 256>>>(W1, W2, M);

    // fork: side stream runs gemm1 while main builds the CSR
    cudaEventRecord(evFork, 0);
    cudaStreamWaitEvent(s2, evFork, 0);

    mma_gemm_kernel<128, false, false, 2><<<(M + 63) / 64, 256, smem1, s2>>>(x, w1hi, w1lo, h1s, M);
    cudaEventRecord(evG1, s2);

    degree_kernel<<<(E + 255) / 256, 256>>>(cols, E);
    scan_pass1<<<nb, 256>>>(bsum, M);
    scan_pass3<<<nb, 1024>>>(bsum, M, nb);
    place_kernel<<<(E + 255) / 256, 256>>>(rows, cols, E);

    // join: agg1 needs CSR + dis (main) and h1s (side)
    cudaStreamWaitEvent(0, evG1, 0);

    agg1_kernel<<<(M * 32 + 255) / 256, 256>>>(b1, M);
    mma_gemm_kernel<64, true, true, 3><<<(M + 63) / 64, 256, smem2>>>(h1f, w2hi, w2lo, h2s, M);
    agg2_kernel<<<(M * 16 + 255) / 256, 256>>>(out, b2, M);
}

// round 16
// speedup vs baseline: 1.1058x; 1.0223x over previous
#include <cuda_runtime.h>
#include <cuda_fp16.h>
#include <cuda_bf16.h>
#include <mma.h>
#include <cstddef>

#define NN    100000
#define FIN   128
#define FHID  128
#define FOUT  64
#define EMAX  1600000

using namespace nvcuda;

// ---------------- static scratch ------------------------------------------
__device__ int   g_deg[NN];
__device__ int   g_offs[NN];
__device__ int   g_cursor[NN];
__device__ int   g_csr[EMAX];
__device__ float g_dis[NN];
__device__ __align__(128) __half g_h1s[(size_t)NN * FHID];  // fp16 UNSCALED x@W1
__device__ __align__(128) __half g_h1f[(size_t)NN * FHID];  // fp16 layer-1 output
__device__ __align__(128) __half g_h2s[(size_t)NN * FOUT];  // fp16 dis*(h1f@W2)
__device__ int   g_bsum[1024];
__device__ __align__(128) __nv_bfloat16 g_w1hi[FIN * FHID];
__device__ __align__(128) __nv_bfloat16 g_w1lo[FIN * FHID];
__device__ __align__(128) __nv_bfloat16 g_w2hi[FHID * FOUT];
__device__ __align__(128) __nv_bfloat16 g_w2lo[FHID * FOUT];

// ---------------- helpers ---------------------------------------------------
__device__ __forceinline__ void acc_h4(float4& s, uint2 v) {
    float2 fa = __half22float2(*(__half2*)&v.x);
    float2 fb = __half22float2(*(__half2*)&v.y);
    s.x += fa.x; s.y += fa.y; s.z += fb.x; s.w += fb.y;
}
__device__ __forceinline__ void acc_h4s(float4& s, uint2 v, float d) {
    float2 fa = __half22float2(*(__half2*)&v.x);
    float2 fb = __half22float2(*(__half2*)&v.y);
    s.x = fmaf(d, fa.x, s.x); s.y = fmaf(d, fa.y, s.y);
    s.z = fmaf(d, fb.x, s.z); s.w = fmaf(d, fb.y, s.w);
}
__device__ __forceinline__ uint2 pack_h4(float a, float b, float c, float d) {
    uint2 r;
    __half2 h0 = __floats2half2_rn(a, b);
    __half2 h1 = __floats2half2_rn(c, d);
    r.x = *(unsigned*)&h0;
    r.y = *(unsigned*)&h1;
    return r;
}
__device__ __forceinline__ void bsplit(float x, __nv_bfloat16& hi, __nv_bfloat16& lo) {
    hi = __float2bfloat16_rn(x);
    lo = __float2bfloat16_rn(x - __bfloat162float(hi));
}
__device__ __forceinline__ void cp_async16(void* dst, const void* src) {
    unsigned d = (unsigned)__cvta_generic_to_shared(dst);
    asm volatile("cp.async.cg.shared.global [%0], [%1], 16;" :: "r"(d), "l"(src));
}
__device__ __forceinline__ void cp_async_commit() {
    asm volatile("cp.async.commit_group;");
}
__device__ __forceinline__ void cp_async_wait0() {
    asm volatile("cp.async.wait_group 0;" ::: "memory");
}

// ---------------- pre-fork: W pre-split + deg zero ---------------------------
__global__ void wsplit_zero_kernel(const float* __restrict__ W1,
                                   const float* __restrict__ W2, int M) {
    int t = blockIdx.x * blockDim.x + threadIdx.x;
    if (t < FIN * FHID) bsplit(W1[t], g_w1hi[t], g_w1lo[t]);
    if (t < FHID * FOUT) bsplit(W2[t], g_w2hi[t], g_w2lo[t]);
    if (t < M) g_deg[t] = 0;
}

// ---------------- degree --------------------------------------------------
__global__ void degree_kernel(const int* __restrict__ col, int E) {
    int t = blockIdx.x * blockDim.x + threadIdx.x;
    if (t < E) atomicAdd(&g_deg[col[t]], 1);
}

// ---------------- 2-pass exclusive scan over g_deg --------------------------
__global__ void scan_pass1(int* __restrict__ bsum, int M) {
    __shared__ int sh[8];
    int b = blockIdx.x, t = threadIdx.x;
    int base = b * 1024;
    int v = 0;
#pragma unroll
    for (int k = 0; k < 4; k++) {
        int i = base + t + k * 256;
        if (i < M) v += g_deg[i];
    }
#pragma unroll
    for (int d = 16; d; d >>= 1) v += __shfl_down_sync(0xffffffffu, v, d);
    if ((t & 31) == 0) sh[t >> 5] = v;
    __syncthreads();
    if (t < 8) {
        int x = sh[t];
#pragma unroll
        for (int d = 4; d; d >>= 1) x += __shfl_down_sync(0xffu, x, d);
        if (t == 0) bsum[b] = x;
    }
}
__global__ void scan_pass3(const int* __restrict__ bsum, int M, int nb) {
    __shared__ int wsum[32];
    __shared__ int baseSum;
    int t = threadIdx.x, b = blockIdx.x;
    if (t < 32) {
        int acc = 0;
        for (int i = t; i < b; i += 32) acc += bsum[i];
#pragma unroll
        for (int d = 16; d; d >>= 1) acc += __shfl_down_sync(0xffffffffu, acc, d);
        if (t == 0) baseSum = acc;
    }
    int i = b * 1024 + t;
    int v = (i < M) ? g_deg[i] : 0;
    int lane = t & 31, wid = t >> 5;
    int inc = v;
#pragma unroll
    for (int d = 1; d < 32; d <<= 1) {
        int n = __shfl_up_sync(0xffffffffu, inc, d);
        if (lane >= d) inc += n;
    }
    if (lane == 31) wsum[wid] = inc;
    __syncthreads();
    if (wid == 0) {
        int x = wsum[lane];
        int ix = x;
#pragma unroll
        for (int d = 1; d < 32; d <<= 1) {
            int n = __shfl_up_sync(0xffffffffu, ix, d);
            if (lane >= d) ix += n;
        }
        wsum[lane] = ix - x;
    }
    __syncthreads();
    if (i < M) {
        int excl = inc - v + wsum[wid] + baseSum;
        g_offs[i]   = excl;
        g_cursor[i] = excl;
        g_dis[i]    = rsqrtf((float)(v + 1));
    }
}

// ---------------- CSR placement -------------------------------------------
__global__ void place_kernel(const int* __restrict__ rows,
                             const int* __restrict__ cols, int E) {
    int e = blockIdx.x * blockDim.x + threadIdx.x;
    if (e < E) {
        int c = cols[e];
        int p = atomicAdd(&g_cursor[c], 1);
        g_csr[p] = rows[e];
    }
}

// -------- 3xBF16 tensor GEMM (persistent tiles): Ch = half([dis *](A@W)) ----
// W staged ONCE per CTA; M-tiles iterated grid-stride.
template <int BN, bool SCALE, bool HALFA, int MINB>
__global__ void __launch_bounds__(256, MINB)
mma_gemm_kernel(const void* __restrict__ Araw,
                const __nv_bfloat16* __restrict__ Whi,
                const __nv_bfloat16* __restrict__ Wlo,
                __half* __restrict__ Ch, int M)
{
    constexpr int BM  = 64;
    constexpr int K   = 128;
    constexpr int LDA = K + 8;
    constexpr int LDB = BN + 8;
    constexpr int LDC = BN + 4;
    constexpr int FM  = 2, FN = BN / 64;

    extern __shared__ char smem[];
    __nv_bfloat16* Ahi = (__nv_bfloat16*)smem;
    __nv_bfloat16* Alo = Ahi + BM * LDA;
    __nv_bfloat16* Bhi = Alo + BM * LDA;
    __nv_bfloat16* Blo = Bhi + K * LDB;
    float*         Cs  = (float*)smem;          // aliases A region

    const int tid  = threadIdx.x;
    const int warp = tid >> 5;
    const int wm   = warp >> 2;
    const int wn   = warp & 3;
    const int row0 = wm * 32;
    const int col0 = wn * (BN / 4);

    // ---- stage W hi/lo ONCE via cp.async ----
    for (int i = tid; i < K * (BN / 8); i += 256) {
        int r  = i / (BN / 8);
        int c8 = (i % (BN / 8)) << 3;
        cp_async16(Bhi + r * LDB + c8, Whi + (size_t)r * BN + c8);
        cp_async16(Blo + r * LDB + c8, Wlo + (size_t)r * BN + c8);
    }
    cp_async_commit();

    const int ntiles = (M + BM - 1) / BM;
    bool firstTile = true;

    for (int tile = blockIdx.x; tile < ntiles; tile += gridDim.x) {
        const int bm0 = tile * BM;

        if (!firstTile) __syncthreads();     // prior epilogue done with Cs (=A region)

        // ---- load + split A tile (64 x 128) ----
#pragma unroll
        for (int p = 0; p < 8; p++) {
            int i  = tid + p * 256;
            int r  = i >> 5;
            int c4 = (i & 31) << 2;
            float4 v = make_float4(0.f, 0.f, 0.f, 0.f);
            if (bm0 + r < M) {
                if (HALFA) {
                    const __half* Ah = (const __half*)Araw;
                    uint2 u = *(const uint2*)(Ah + (size_t)(bm0 + r) * K + c4);
                    float2 fa = __half22float2(*(__half2*)&u.x);
                    float2 fb = __half22float2(*(__half2*)&u.y);
                    v = make_float4(fa.x, fa.y, fb.x, fb.y);
                } else {
                    const float* Af = (const float*)Araw;
                    v = *(const float4*)(Af + (size_t)(bm0 + r) * K + c4);
                }
            }
            __nv_bfloat16 h0, l0, h1, l1, h2, l2, h3, l3;
            bsplit(v.x, h0, l0); bsplit(v.y, h1, l1);
            bsplit(v.z, h2, l2); bsplit(v.w, h3, l3);
            __nv_bfloat162 hh0 = {h0, h1}, hh1 = {h2, h3};
            __nv_bfloat162 ll0 = {l0, l1}, ll1 = {l2, l3};
            uint2 hp = {*(unsigned*)&hh0, *(unsigned*)&hh1};
            uint2 lp = {*(unsigned*)&ll0, *(unsigned*)&ll1};
            *(uint2*)(Ahi + r * LDA + c4) = hp;
            *(uint2*)(Alo + r * LDA + c4) = lp;
        }
        if (firstTile) { cp_async_wait0(); firstTile = false; }
        __syncthreads();

        wmma::fragment<wmma::accumulator, 16, 16, 16, float> c[FM][FN];
#pragma unroll
        for (int i = 0; i < FM; i++)
#pragma unroll
            for (int j = 0; j < FN; j++) wmma::fill_fragment(c[i][j], 0.f);

#pragma unroll
        for (int kk = 0; kk < K; kk += 16) {
            wmma::fragment<wmma::matrix_b, 16, 16, 16, __nv_bfloat16, wmma::row_major> bh[FN], bl[FN];
#pragma unroll
            for (int j = 0; j < FN; j++) {
                wmma::load_matrix_sync(bh[j], Bhi + kk * LDB + col0 + j * 16, LDB);
                wmma::load_matrix_sync(bl[j], Blo + kk * LDB + col0 + j * 16, LDB);
            }
#pragma unroll
            for (int i = 0; i < FM; i++) {
                wmma::fragment<wmma::matrix_a, 16, 16, 16, __nv_bfloat16, wmma::row_major> ah, al;
                wmma::load_matrix_sync(ah, Ahi + (row0 + i * 16) * LDA + kk, LDA);
                wmma::load_matrix_sync(al, Alo + (row0 + i * 16) * LDA + kk, LDA);
#pragma unroll
                for (int j = 0; j < FN; j++) {
                    wmma::mma_sync(c[i][j], ah, bh[j], c[i][j]);
                    wmma::mma_sync(c[i][j], ah, bl[j], c[i][j]);
                    wmma::mma_sync(c[i][j], al, bh[j], c[i][j]);
                }
            }
        }

        __syncthreads();                      // done reading A; reuse as Cs
#pragma unroll
        for (int i = 0; i < FM; i++)
#pragma unroll
            for (int j = 0; j < FN; j++)
                wmma::store_matrix_sync(Cs + (row0 + i * 16) * LDC + col0 + j * 16,
                                        c[i][j], LDC, wmma::mem_row_major);
        __syncthreads();

        for (int i = tid; i < BM * (BN / 4); i += 256) {
            int r  = i / (BN / 4);
            int c4 = (i % (BN / 4)) << 2;
            int gr = bm0 + r;
            if (gr < M) {
                float d = SCALE ? g_dis[gr] : 1.0f;
                const float* cp = Cs + r * LDC + c4;
                uint2 p = pack_h4(cp[0] * d, cp[1] * d, cp[2] * d, cp[3] * d);
                *(uint2*)(Ch + (size_t)gr * BN + c4) = p;
            }
        }
    }
}

// ------- agg1: warp/node; h1s UNSCALED; dis[src] applied at gather ----------
__global__ void __launch_bounds__(256)
agg1_kernel(const float* __restrict__ b1, int M) {
    int w    = (blockIdx.x * 256 + threadIdx.x) >> 5;
    int lane = threadIdx.x & 31;
    if (w >= M) return;
    int beg = g_offs[w];
    int end = beg + g_deg[w];
    float dw = g_dis[w];
    const uint2* h = (const uint2*)g_h1s;
    float4 s = make_float4(0.f, 0.f, 0.f, 0.f);
    acc_h4s(s, __ldg(h + (size_t)w * 32 + lane), dw);   // self * dis[w]
    for (int j0 = beg; j0 < end; j0 += 32) {
        int rem = end - j0;
        int cnt = rem < 32 ? rem : 32;
        int   myi = 0;
        float myd = 0.f;
        if (lane < rem) {
            myi = __ldg(g_csr + j0 + lane);
            myd = __ldg(g_dis + myi);
        }
        int j = 0;
        for (; j + 4 <= cnt; j += 4) {
            int   s0 = __shfl_sync(0xffffffffu, myi, j);
            int   s1 = __shfl_sync(0xffffffffu, myi, j + 1);
            int   s2 = __shfl_sync(0xffffffffu, myi, j + 2);
            int   s3 = __shfl_sync(0xffffffffu, myi, j + 3);
            float d0 = __shfl_sync(0xffffffffu, myd, j);
            float d1 = __shfl_sync(0xffffffffu, myd, j + 1);
            float d2 = __shfl_sync(0xffffffffu, myd, j + 2);
            float d3 = __shfl_sync(0xffffffffu, myd, j + 3);
            uint2 v0 = __ldg(h + (size_t)s0 * 32 + lane);
            uint2 v1 = __ldg(h + (size_t)s1 * 32 + lane);
            uint2 v2 = __ldg(h + (size_t)s2 * 32 + lane);
            uint2 v3 = __ldg(h + (size_t)s3 * 32 + lane);
            acc_h4s(s, v0, d0); acc_h4s(s, v1, d1);
            acc_h4s(s, v2, d2); acc_h4s(s, v3, d3);
        }
        for (; j < cnt; j++) {
            int   si = __shfl_sync(0xffffffffu, myi, j);
            float di = __shfl_sync(0xffffffffu, myd, j);
            acc_h4s(s, __ldg(h + (size_t)si * 32 + lane), di);
        }
    }
    float4 b = __ldg((const float4*)b1 + lane);
    float ox = fmaxf(fmaf(dw, s.x, b.x), 0.f);
    float oy = fmaxf(fmaf(dw, s.y, b.y), 0.f);
    float oz = fmaxf(fmaf(dw, s.z, b.z), 0.f);
    float ow = fmaxf(fmaf(dw, s.w, b.w), 0.f);
    ((uint2*)g_h1f)[(size_t)w * 32 + lane] = pack_h4(ox, oy, oz, ow);
}

// ------- agg2: half-warp/node, out = dis*(sum_nbr h2s + h2s[self]) + b2 ----
__global__ void __launch_bounds__(256)
agg2_kernel(float* __restrict__ out, const float* __restrict__ b2, int M) {
    int tid  = blockIdx.x * 256 + threadIdx.x;
    int node = tid >> 4;
    int lane = threadIdx.x & 31;
    int l16  = lane & 15;
    unsigned mask = 0xFFFFu << (lane & 16);
    bool valid = node < M;
    int beg = 0, end = 0;
    if (valid) { beg = g_offs[node]; end = beg + g_deg[node]; }
    const uint2* h = (const uint2*)g_h2s;
    float4 s = make_float4(0.f, 0.f, 0.f, 0.f);
    if (valid) acc_h4(s, __ldg(h + (size_t)node * 16 + l16));
    for (int j0 = beg; j0 < end; j0 += 16) {
        int rem = end - j0;
        int cnt = rem < 16 ? rem : 16;
        int myi = (l16 < rem) ? __ldg(g_csr + j0 + l16) : 0;
        int j = 0;
        for (; j + 4 <= cnt; j += 4) {
            int s0 = __shfl_sync(mask, myi, j,     16);
            int s1 = __shfl_sync(mask, myi, j + 1, 16);
            int s2 = __shfl_sync(mask, myi, j + 2, 16);
            int s3 = __shfl_sync(mask, myi, j + 3, 16);
            uint2 v0 = __ldg(h + (size_t)s0 * 16 + l16);
            uint2 v1 = __ldg(h + (size_t)s1 * 16 + l16);
            uint2 v2 = __ldg(h + (size_t)s2 * 16 + l16);
            uint2 v3 = __ldg(h + (size_t)s3 * 16 + l16);
            acc_h4(s, v0); acc_h4(s, v1); acc_h4(s, v2); acc_h4(s, v3);
        }
        for (; j < cnt; j++) {
            int si = __shfl_sync(mask, myi, j, 16);
            acc_h4(s, __ldg(h + (size_t)si * 16 + l16));
        }
    }
    if (valid) {
        float  d = g_dis[node];
        float4 b = __ldg((const float4*)b2 + l16);
        float4 o;
        o.x = fmaf(d, s.x, b.x);
        o.y = fmaf(d, s.y, b.y);
        o.z = fmaf(d, s.z, b.z);
        o.w = fmaf(d, s.w, b.w);
        ((float4*)out)[(size_t)node * 16 + l16] = o;
    }
}

// ---------------- launch ----------------------------------------------------
extern "C" void kernel_launch(void* const* d_in, const int* in_sizes, int n_in,
                              void* d_out, int out_size) {
    const float* x  = (const float*)d_in[0];
    const int*   ei = (const int*)  d_in[1];
    const float* W1 = (const float*)d_in[2];
    const float* b1 = (const float*)d_in[3];
    const float* W2 = (const float*)d_in[4];
    const float* b2 = (const float*)d_in[5];
    float* out = (float*)d_out;

    const int M = in_sizes[0] / FIN;
    const int E = in_sizes[1] / 2;
    const int* rows = ei;
    const int* cols = ei + E;

    __half *h1s, *h1f, *h2s;
    int* bsum;
    __nv_bfloat16 *w1hi, *w1lo, *w2hi, *w2lo;
    cudaGetSymbolAddress((void**)&h1s,  g_h1s);
    cudaGetSymbolAddress((void**)&h1f,  g_h1f);
    cudaGetSymbolAddress((void**)&h2s,  g_h2s);
    cudaGetSymbolAddress((void**)&bsum, g_bsum);
    cudaGetSymbolAddress((void**)&w1hi, g_w1hi);
    cudaGetSymbolAddress((void**)&w1lo, g_w1lo);
    cudaGetSymbolAddress((void**)&w2hi, g_w2hi);
    cudaGetSymbolAddress((void**)&w2lo, g_w2lo);

    const int nb = (M + 1023) / 1024;

    const int smem1 = (2 * 64 * 136 + 2 * 128 * 136) * 2;   // 104448
    const int smem2 = (2 * 64 * 136 + 2 * 128 *  72) * 2;   //  71680
    cudaFuncSetAttribute((const void*)mma_gemm_kernel<128, false, false, 2>,
                         cudaFuncAttributeMaxDynamicSharedMemorySize, smem1);
    cudaFuncSetAttribute((const void*)mma_gemm_kernel<64, true, true, 3>,
                         cudaFuncAttributeMaxDynamicSharedMemorySize, smem2);

    static cudaStream_t s2 = nullptr;
    static cudaEvent_t  evFork = nullptr, evG1 = nullptr;
    if (!s2) {
        cudaStreamCreateWithFlags(&s2, cudaStreamNonBlocking);
        cudaEventCreateWithFlags(&evFork, cudaEventDisableTiming);
        cudaEventCreateWithFlags(&evG1,  cudaEventDisableTiming);
    }

    // pre-fork: one kernel does W split + deg zero (both branches need it)
    int preN = (M > FIN * FHID) ? M : FIN * FHID;
    wsplit_zero_kernel<<<(preN + 255) / 256, 256>>>(W1, W2, M);

    // fork: side stream runs gemm1 while main builds the CSR
    cudaEventRecord(evFork, 0);
    cudaStreamWaitEvent(s2, evFork, 0);

    const int tiles1 = (M + 63) / 64;
    const int grid1  = tiles1 < 296 ? tiles1 : 296;          // 2 CTAs/SM persistent
    mma_gemm_kernel<128, false, false, 2><<<grid1, 256, smem1, s2>>>(x, w1hi, w1lo, h1s, M);
    cudaEventRecord(evG1, s2);

    degree_kernel<<<(E + 255) / 256, 256>>>(cols, E);
    scan_pass1<<<nb, 256>>>(bsum, M);
    scan_pass3<<<nb, 1024>>>(bsum, M, nb);
    place_kernel<<<(E + 255) / 256, 256>>>(rows, cols, E);

    // join: agg1 needs CSR + dis (main) and h1s (side)
    cudaStreamWaitEvent(0, evG1, 0);

    agg1_kernel<<<(M * 32 + 255) / 256, 256>>>(b1, M);

    const int tiles2 = (M + 63) / 64;
    const int grid2  = tiles2 < 444 ? tiles2 : 444;          // 3 CTAs/SM persistent
    mma_gemm_kernel<64, true, true, 3><<<grid2, 256, smem2>>>(h1f, w2hi, w2lo, h2s, M);

    agg2_kernel<<<(M * 16 + 255) / 256, 256>>>(out, b2, M);
}